// round 5
// baseline (speedup 1.0000x reference)
#include <cuda_runtime.h>
#include <cuda_bf16.h>
#include <math.h>

#define D 2048
#define H 8192
#define NL 4

// Scratch (device globals; no allocation allowed)
__device__ float g_x[D];     // current layer input
__device__ float g_xn[D];    // ln1(x)
__device__ float g_rab[D];   // rsig * (a/b)
__device__ float g_sx[D];    // x + rwkv
__device__ float g_dx[D];    // x2n + sffn*tmk
__device__ float g_xr[D];    // x2n + sffn*tmr
__device__ float g_kk[H];    // relu(kffn@dx)^2
__device__ float g_r[D];     // sigmoid(rffn@xr)

__device__ __forceinline__ float warp_sum(float v) {
#pragma unroll
    for (int o = 16; o; o >>= 1) v += __shfl_xor_sync(0xffffffffu, v, o);
    return v;
}

__device__ __forceinline__ float d4(const float4 a, const float4 b) {
    return a.x * b.x + a.y * b.y + a.z * b.z + a.w * b.w;
}

// 256-thread block sum
__device__ __forceinline__ float block_sum(float v, float* sred) {
    v = warp_sum(v);
    int w = threadIdx.x >> 5, lane = threadIdx.x & 31;
    if (lane == 0) sred[w] = v;
    __syncthreads();
    float t = (threadIdx.x < 8) ? sred[threadIdx.x] : 0.f;
    if (w == 0) {
        t = warp_sum(t);
        if (lane == 0) sred[0] = t;
    }
    __syncthreads();
    float r = sred[0];
    __syncthreads();
    return r;
}

// One forced batch of 8 independent LDG.128 (256-float4 segment), then FMAs.
__device__ __forceinline__ float chunk8(const float4* __restrict__ r4,
                                        const float4* __restrict__ s4,
                                        int off, int lane) {
    float4 w[8];
#pragma unroll
    for (int u = 0; u < 8; u++) w[u] = __ldcs(r4 + off + lane + u * 32);
    float a0 = 0.f, a1 = 0.f;
#pragma unroll
    for (int u = 0; u < 8; u += 2) {
        a0 += d4(w[u],     s4[off + lane + u * 32]);
        a1 += d4(w[u + 1], s4[off + lane + (u + 1) * 32]);
    }
    return a0 + a1;
}

__global__ __launch_bounds__(256) void kcopy(const float* __restrict__ x) {
    int i = blockIdx.x * 256 + threadIdx.x;
    if (i < D) g_x[i] = x[i];
}

// LN1: one block. xn = ln(g_x)*w+b -> g_xn and out_state row 5l+0.
__global__ __launch_bounds__(256) void kLN1(
    const float* __restrict__ ln1w, const float* __restrict__ ln1b,
    float* __restrict__ out_state, int l)
{
    __shared__ float sred[9];
    int tid = threadIdx.x;
    float lsum = 0.f;
    for (int i = tid; i < D; i += 256) lsum += g_x[i];
    float m = block_sum(lsum, sred) * (1.f / D);
    float lv = 0.f;
    for (int i = tid; i < D; i += 256) { float d0 = g_x[i] - m; lv += d0 * d0; }
    float var = block_sum(lv, sred) * (1.f / D);
    float rs = rsqrtf(var + 1e-5f);
    const float* w = ln1w + (size_t)l * D;
    const float* b = ln1b + (size_t)l * D;
    float* xnrow = out_state + (size_t)(5 * l + 0) * D;
    for (int i = tid; i < D; i += 256) {
        float xn = (g_x[i] - m) * rs * w[i] + b[i];
        g_xn[i] = xn;
        xnrow[i] = xn;
    }
}

// Stage B: rrk = key@xn + keymul@state0 + WKV epilogue.
// grid = D/8 = 256 blocks x 256 threads; warp per output index i.
__global__ __launch_bounds__(256) void kB(
    const float* __restrict__ state,
    const float* __restrict__ key, const float* __restrict__ keymul,
    const float* __restrict__ td, const float* __restrict__ tf,
    float* __restrict__ out_state, int l)
{
    __shared__ __align__(16) float s_xn[D];
    __shared__ __align__(16) float s_sr[D];
    int tid = threadIdx.x;
    const float* srow = state + (size_t)(5 * l) * D;
    for (int i = tid; i < D; i += 256) {
        s_xn[i] = g_xn[i];
        s_sr[i] = srow[i];
    }
    __syncthreads();
    int warp = tid >> 5, lane = tid & 31;
    int i = blockIdx.x * 8 + warp;
    const float4* xn4 = (const float4*)s_xn;
    const float4* sr4 = (const float4*)s_sr;
    float acc[3];
#pragma unroll
    for (int j = 0; j < 3; j++) {
        const float4* kr = (const float4*)(key    + ((((size_t)l * 3 + j) * D + i) * D));
        const float4* mr = (const float4*)(keymul + ((((size_t)l * 3 + j) * D + i) * D));
        float a = chunk8(kr, xn4, 0, lane) + chunk8(kr, xn4, 256, lane)
                + chunk8(mr, sr4, 0, lane) + chunk8(mr, sr4, 256, lane);
        acc[j] = warp_sum(a);
    }
    if (lane == 0) {
        float k = acc[0], v = acc[1], rr = acc[2];
        float aa = state[(size_t)(5 * l + 1) * D + i];
        float bb = state[(size_t)(5 * l + 2) * D + i];
        float pp = state[(size_t)(5 * l + 3) * D + i];
        float tfi = tf[(size_t)l * D + i];
        float tdi = td[(size_t)l * D + i];
        float rsig = 1.f / (1.f + expf(-rr));
        float ww = tfi + k;
        float q = fmaxf(pp, ww);
        float e1 = expf(pp - q), e2 = expf(ww - q);
        float a_ = e1 * aa + e2 * v;
        float b_ = e1 * bb + e2;
        float ww2 = pp + tdi;
        float q2 = fmaxf(ww2, k);
        float f1 = expf(ww2 - q2), f2 = expf(k - q2);
        g_rab[i] = rsig * (a_ / b_);
        out_state[(size_t)(5 * l + 1) * D + i] = f1 * aa + f2 * v;
        out_state[(size_t)(5 * l + 2) * D + i] = f1 * bb + f2;
        out_state[(size_t)(5 * l + 3) * D + i] = q2;
    }
}

// Stage C: sx = x + outputv[l] @ g_rab.  grid = 256 x 256, warp/row.
__global__ __launch_bounds__(256) void kC(const float* __restrict__ ow, int l)
{
    __shared__ __align__(16) float s_v[D];
    for (int i = threadIdx.x; i < D; i += 256) s_v[i] = g_rab[i];
    __syncthreads();
    int warp = threadIdx.x >> 5, lane = threadIdx.x & 31;
    int i = blockIdx.x * 8 + warp;
    const float4* r4 = (const float4*)(ow + ((size_t)l * D + i) * D);
    const float4* v4 = (const float4*)s_v;
    float a = warp_sum(chunk8(r4, v4, 0, lane) + chunk8(r4, v4, 256, lane));
    if (lane == 0) g_sx[i] = g_x[i] + a;
}

// LN2: one block. x2n = ln(g_sx)*w+b; g_dx = x2n + sf*tmk; g_xr = x2n + sf*tmr.
__global__ __launch_bounds__(256) void kLN2(
    const float* __restrict__ state,
    const float* __restrict__ ln2w, const float* __restrict__ ln2b,
    const float* __restrict__ tmk, const float* __restrict__ tmr,
    float* __restrict__ out_state, int l)
{
    __shared__ float sred[9];
    int tid = threadIdx.x;
    float lsum = 0.f;
    for (int i = tid; i < D; i += 256) lsum += g_sx[i];
    float m = block_sum(lsum, sred) * (1.f / D);
    float lv = 0.f;
    for (int i = tid; i < D; i += 256) { float d0 = g_sx[i] - m; lv += d0 * d0; }
    float var = block_sum(lv, sred) * (1.f / D);
    float rs = rsqrtf(var + 1e-5f);
    const float* w  = ln2w + (size_t)l * D;
    const float* b  = ln2b + (size_t)l * D;
    const float* sf = state + (size_t)(5 * l + 4) * D;
    const float* tk = tmk + (size_t)l * D;
    const float* tr = tmr + (size_t)l * D;
    float* x2row = out_state + (size_t)(5 * l + 4) * D;
    for (int i = tid; i < D; i += 256) {
        float x2n = (g_sx[i] - m) * rs * w[i] + b[i];
        float sfi = sf[i];
        x2row[i] = x2n;
        g_dx[i] = x2n + sfi * tk[i];
        g_xr[i] = x2n + sfi * tr[i];
    }
}

// Stage E matvecs: kk = relu(kffn@dx)^2 ; r = sigmoid(rffn@xr).
// grid = (H+D)/8 = 1280 blocks x 256 threads; warp per output.
__global__ __launch_bounds__(256) void kE(
    const float* __restrict__ kffn, const float* __restrict__ rffn, int l)
{
    __shared__ __align__(16) float s_dx[D];
    __shared__ __align__(16) float s_xr[D];
    for (int i = threadIdx.x; i < D; i += 256) {
        s_dx[i] = g_dx[i];
        s_xr[i] = g_xr[i];
    }
    __syncthreads();
    int warp = threadIdx.x >> 5, lane = threadIdx.x & 31;
    int o = blockIdx.x * 8 + warp;
    if (o < H) {
        const float4* r4 = (const float4*)(kffn + ((size_t)l * H + o) * D);
        const float4* v4 = (const float4*)s_dx;
        float a = warp_sum(chunk8(r4, v4, 0, lane) + chunk8(r4, v4, 256, lane));
        if (lane == 0) { float rl = fmaxf(a, 0.f); g_kk[o] = rl * rl; }
    } else {
        int i = o - H;
        const float4* r4 = (const float4*)(rffn + ((size_t)l * D + i) * D);
        const float4* v4 = (const float4*)s_xr;
        float a = warp_sum(chunk8(r4, v4, 0, lane) + chunk8(r4, v4, 256, lane));
        if (lane == 0) g_r[i] = 1.f / (1.f + expf(-a));
    }
}

// Stage F: out = sx + r * (vffn[l] @ kk).  grid = 256 x 256, warp/row (32KB/row).
__global__ __launch_bounds__(256) void kF(const float* __restrict__ vffn,
                                          float* __restrict__ xout, int l, int last)
{
    __shared__ __align__(16) float s_kk[H];  // 32 KB
    for (int i = threadIdx.x; i < H; i += 256) s_kk[i] = g_kk[i];
    __syncthreads();
    int warp = threadIdx.x >> 5, lane = threadIdx.x & 31;
    int i = blockIdx.x * 8 + warp;
    const float4* r4 = (const float4*)(vffn + ((size_t)l * D + i) * H);
    const float4* v4 = (const float4*)s_kk;
    float a = 0.f;
#pragma unroll
    for (int c = 0; c < 8; c++)
        a += chunk8(r4, v4, c * 256, lane);
    a = warp_sum(a);
    if (lane == 0) {
        float val = g_sx[i] + g_r[i] * a;
        if (last) xout[i] = val;
        else g_x[i] = val;
    }
}

extern "C" void kernel_launch(void* const* d_in, const int* in_sizes, int n_in,
                              void* d_out, int out_size)
{
    const float* x      = (const float*)d_in[0];
    const float* state  = (const float*)d_in[1];
    const float* ln1w   = (const float*)d_in[2];
    const float* ln1b   = (const float*)d_in[3];
    const float* ln2w   = (const float*)d_in[4];
    const float* ln2b   = (const float*)d_in[5];
    const float* td     = (const float*)d_in[6];
    const float* tf     = (const float*)d_in[7];
    const float* key    = (const float*)d_in[8];
    const float* keymul = (const float*)d_in[9];
    const float* ow     = (const float*)d_in[10];
    const float* tmk    = (const float*)d_in[11];
    const float* tmr    = (const float*)d_in[12];
    const float* kffn   = (const float*)d_in[13];
    const float* rffn   = (const float*)d_in[14];
    const float* vffn   = (const float*)d_in[15];

    float* out       = (float*)d_out;
    float* out_x     = out;       // [D]
    float* out_state = out + D;   // [L*5*D]

    kcopy<<<(D + 255) / 256, 256>>>(x);
    for (int l = 0; l < NL; l++) {
        kLN1<<<1, 256>>>(ln1w, ln1b, out_state, l);
        kB<<<D / 8, 256>>>(state, key, keymul, td, tf, out_state, l);
        kC<<<D / 8, 256>>>(ow, l);
        kLN2<<<1, 256>>>(state, ln2w, ln2b, tmk, tmr, out_state, l);
        kE<<<(H + D) / 8, 256>>>(kffn, rffn, l);
        kF<<<D / 8, 256>>>(vffn, out_x, l, (l == NL - 1) ? 1 : 0);
    }
}

// round 7
// speedup vs baseline: 1.1144x; 1.1144x over previous
#include <cuda_runtime.h>
#include <cuda_bf16.h>
#include <math.h>
#include <stdint.h>

#define D 2048
#define H 8192
#define NL 4
#define GRID 148
#define WTOT (GRID * 8)

// Scratch (device globals; no allocation allowed)
__device__ float g_x[D];          // current layer input
__device__ float g_rrk[3 * D];    // key@xn + keymul@state0 partials
__device__ float g_sx[D];         // x + rwkv
__device__ float g_kk[H];         // relu(kffn@dx)^2
__device__ float g_r[D];          // sigmoid(rffn@xr)

__device__ __forceinline__ float warp_sum(float v) {
#pragma unroll
    for (int o = 16; o; o >>= 1) v += __shfl_xor_sync(0xffffffffu, v, o);
    return v;
}

__device__ __forceinline__ float d4(const float4 a, const float4 b) {
    return a.x * b.x + a.y * b.y + a.z * b.z + a.w * b.w;
}

__device__ __forceinline__ float block_sum(float v, float* sred) {
    v = warp_sum(v);
    int w = threadIdx.x >> 5, lane = threadIdx.x & 31;
    if (lane == 0) sred[w] = v;
    __syncthreads();
    float t = (threadIdx.x < 8) ? sred[threadIdx.x] : 0.f;
    if (w == 0) {
        t = warp_sum(t);
        if (lane == 0) sred[0] = t;
    }
    __syncthreads();
    float r = sred[0];
    __syncthreads();
    return r;
}

// ---- cp.async warp-owned pipeline helpers (8KB rows = 512 float4) ----
__device__ __forceinline__ void cp_row8k(float4* sdst, const float4* __restrict__ gsrc,
                                         int lane) {
#pragma unroll
    for (int u = 0; u < 16; u++) {
        unsigned int s = (unsigned int)__cvta_generic_to_shared(sdst + lane + u * 32);
        asm volatile("cp.async.cg.shared.global [%0], [%1], 16;\n"
                     :: "r"(s), "l"(gsrc + lane + u * 32));
    }
    asm volatile("cp.async.commit_group;\n");
}
__device__ __forceinline__ void cp_commit_empty() {
    asm volatile("cp.async.commit_group;\n");
}
__device__ __forceinline__ void cp_wait1() {
    asm volatile("cp.async.wait_group 1;\n" ::: "memory");
    __syncwarp();
}

__device__ __forceinline__ float dot_row8k(const float4* __restrict__ sbuf,
                                           const float4* __restrict__ svec, int lane) {
    float a0 = 0.f, a1 = 0.f, a2 = 0.f, a3 = 0.f;
#pragma unroll
    for (int u = 0; u < 16; u += 4) {
        a0 += d4(sbuf[lane + u * 32],       svec[lane + u * 32]);
        a1 += d4(sbuf[lane + (u + 1) * 32], svec[lane + (u + 1) * 32]);
        a2 += d4(sbuf[lane + (u + 2) * 32], svec[lane + (u + 2) * 32]);
        a3 += d4(sbuf[lane + (u + 3) * 32], svec[lane + (u + 3) * 32]);
    }
    return (a0 + a1) + (a2 + a3);
}

__global__ __launch_bounds__(256) void kcopy(const float* __restrict__ x) {
    int i = blockIdx.x * 256 + threadIdx.x;
    if (i < D) g_x[i] = x[i];
}

// Stage B: LN1 (redundant per block) + g_rrk[j*D+i] = key[l,j,i,:].xn + keymul[l,j,i,:].state0
// grid = 148 x 256. Warp-owned cp.async pipeline over tile pairs.
__global__ __launch_bounds__(256, 1) void kB(
    const float* __restrict__ state,
    const float* __restrict__ ln1w, const float* __restrict__ ln1b,
    const float* __restrict__ key, const float* __restrict__ keymul,
    float* __restrict__ out_state, int l)
{
    extern __shared__ __align__(16) float smem[];
    float4* bufs = (float4*)smem;            // 8 warps * 2 * 512 f4
    float* s_xn = smem + 8 * 2 * 2048;       // 2048 f
    float* s_sr = s_xn + 2048;               // 2048 f
    __shared__ float sred[9];
    int tid = threadIdx.x, warp = tid >> 5, lane = tid & 31;

    const float* srow = state + (size_t)(5 * l) * D;
    float ls = 0.f;
    for (int i = tid; i < D; i += 256) {
        float xv = g_x[i];
        s_xn[i] = xv; ls += xv;
        s_sr[i] = srow[i];
    }
    float m = block_sum(ls, sred) * (1.f / D);
    float lv = 0.f;
    for (int i = tid; i < D; i += 256) { float d0 = s_xn[i] - m; lv += d0 * d0; }
    float var = block_sum(lv, sred) * (1.f / D);
    float rs = rsqrtf(var + 1e-5f);
    const float* w = ln1w + (size_t)l * D;
    const float* b = ln1b + (size_t)l * D;
    for (int i = tid; i < D; i += 256)
        s_xn[i] = (s_xn[i] - m) * rs * w[i] + b[i];
    __syncthreads();
    if (blockIdx.x == 0) {
        float* xnrow = out_state + (size_t)(5 * l + 0) * D;
        for (int i = tid; i < D; i += 256) xnrow[i] = s_xn[i];
    }

    int gw = blockIdx.x * 8 + warp;
    float4* b0 = bufs + warp * 1024;
    float4* b1 = b0 + 512;
    // pairs p = gw + q*WTOT < 3*D; tiles t: pair = t>>1, which = t&1 (0=key,1=keymul)
    int npairs = 0;
    for (int p = gw; p < 3 * D; p += WTOT) npairs++;
    int ntiles = 2 * npairs;
    if (ntiles > 0) {
        // tile source address
        auto wsrc = [&](int t) -> const float4* {
            int p = gw + (t >> 1) * WTOT;
            int j = p >> 11, i = p & 2047;
            const float* base = (t & 1) ? keymul : key;
            return (const float4*)(base + ((((size_t)l * 3 + j) * D + i) * (size_t)D));
        };
        cp_row8k(b0, wsrc(0), lane);
        float acc = 0.f;
        for (int t = 0; t < ntiles; t++) {
            if (t + 1 < ntiles) cp_row8k((t & 1) ? b0 : b1, wsrc(t + 1), lane);
            else cp_commit_empty();
            cp_wait1();
            const float4* vec = (const float4*)((t & 1) ? s_sr : s_xn);
            acc += dot_row8k((t & 1) ? b1 : b0, vec, lane);
            if (t & 1) {
                float a = warp_sum(acc);
                int p = gw + (t >> 1) * WTOT;
                if (lane == 0) g_rrk[p] = a;
                acc = 0.f;
            }
        }
    }
}

// Stage C: WKV epilogue (redundant per block) + sx = x + outputv[l] @ rab.
// grid = 148 x 256.
__global__ __launch_bounds__(256, 1) void kC(
    const float* __restrict__ state,
    const float* __restrict__ td, const float* __restrict__ tf,
    const float* __restrict__ ow,
    float* __restrict__ out_state, int l)
{
    extern __shared__ __align__(16) float smem[];
    float4* bufs = (float4*)smem;
    float* s_v = smem + 8 * 2 * 2048;  // rab vec
    int tid = threadIdx.x, warp = tid >> 5, lane = tid & 31;

    for (int i = tid; i < D; i += 256) {
        float k  = g_rrk[i];
        float v  = g_rrk[D + i];
        float rr = g_rrk[2 * D + i];
        float aa = state[(size_t)(5 * l + 1) * D + i];
        float bb = state[(size_t)(5 * l + 2) * D + i];
        float pp = state[(size_t)(5 * l + 3) * D + i];
        float tfi = tf[(size_t)l * D + i];
        float tdi = td[(size_t)l * D + i];
        float rsig = 1.f / (1.f + expf(-rr));
        float ww = tfi + k;
        float q = fmaxf(pp, ww);
        float e1 = expf(pp - q), e2 = expf(ww - q);
        float a_ = e1 * aa + e2 * v;
        float b_ = e1 * bb + e2;
        s_v[i] = rsig * (a_ / b_);
        if (blockIdx.x == 0) {
            float ww2 = pp + tdi;
            float q2 = fmaxf(ww2, k);
            float f1 = expf(ww2 - q2), f2 = expf(k - q2);
            out_state[(size_t)(5 * l + 1) * D + i] = f1 * aa + f2 * v;
            out_state[(size_t)(5 * l + 2) * D + i] = f1 * bb + f2;
            out_state[(size_t)(5 * l + 3) * D + i] = q2;
        }
    }
    __syncthreads();

    int gw = blockIdx.x * 8 + warp;
    float4* b0 = bufs + warp * 1024;
    float4* b1 = b0 + 512;
    const float4* vec = (const float4*)s_v;
    if (gw < D) {
        cp_row8k(b0, (const float4*)(ow + ((size_t)l * D + gw) * D), lane);
        int par = 0;
        for (int r = gw; r < D; r += WTOT) {
            int rn = r + WTOT;
            if (rn < D) cp_row8k(par ? b0 : b1,
                                 (const float4*)(ow + ((size_t)l * D + rn) * D), lane);
            else cp_commit_empty();
            cp_wait1();
            float a = warp_sum(dot_row8k(par ? b1 : b0, vec, lane));
            if (lane == 0) g_sx[r] = g_x[r] + a;
            par ^= 1;
        }
    }
}

// Stage E: LN2 (redundant per block) + kk = relu(kffn@dx)^2 ; r = sigmoid(rffn@xr).
// grid = 148 x 256.
__global__ __launch_bounds__(256, 1) void kE(
    const float* __restrict__ state,
    const float* __restrict__ ln2w, const float* __restrict__ ln2b,
    const float* __restrict__ tmk, const float* __restrict__ tmr,
    const float* __restrict__ kffn, const float* __restrict__ rffn,
    float* __restrict__ out_state, int l)
{
    extern __shared__ __align__(16) float smem[];
    float4* bufs = (float4*)smem;
    float* s_dx = smem + 8 * 2 * 2048;
    float* s_xr = s_dx + 2048;
    __shared__ float sred[9];
    int tid = threadIdx.x, warp = tid >> 5, lane = tid & 31;

    float ls = 0.f;
    for (int i = tid; i < D; i += 256) { float v = g_sx[i]; s_dx[i] = v; ls += v; }
    float m = block_sum(ls, sred) * (1.f / D);
    float lv = 0.f;
    for (int i = tid; i < D; i += 256) { float d0 = s_dx[i] - m; lv += d0 * d0; }
    float var = block_sum(lv, sred) * (1.f / D);
    float rs = rsqrtf(var + 1e-5f);
    const float* w  = ln2w + (size_t)l * D;
    const float* b  = ln2b + (size_t)l * D;
    const float* sf = state + (size_t)(5 * l + 4) * D;
    const float* tk = tmk + (size_t)l * D;
    const float* tr = tmr + (size_t)l * D;
    for (int i = tid; i < D; i += 256) {
        float x2n = (s_dx[i] - m) * rs * w[i] + b[i];
        float sfi = sf[i];
        if (blockIdx.x == 0) out_state[(size_t)(5 * l + 4) * D + i] = x2n;
        s_xr[i] = x2n + sfi * tr[i];
        s_dx[i] = x2n + sfi * tk[i];
    }
    __syncthreads();

    int gw = blockIdx.x * 8 + warp;
    float4* b0 = bufs + warp * 1024;
    float4* b1 = b0 + 512;
    const int NR = H + D;
    auto wrow = [&](int r) -> const float4* {
        if (r < H) return (const float4*)(kffn + ((size_t)l * H + r) * D);
        return (const float4*)(rffn + ((size_t)l * D + (r - H)) * D);
    };
    cp_row8k(b0, wrow(gw), lane);
    int par = 0;
    for (int r = gw; r < NR; r += WTOT) {
        int rn = r + WTOT;
        if (rn < NR) cp_row8k(par ? b0 : b1, wrow(rn), lane);
        else cp_commit_empty();
        cp_wait1();
        const float4* vec = (const float4*)(r < H ? s_dx : s_xr);
        float a = warp_sum(dot_row8k(par ? b1 : b0, vec, lane));
        if (lane == 0) {
            if (r < H) { float rl = fmaxf(a, 0.f); g_kk[r] = rl * rl; }
            else g_r[r - H] = 1.f / (1.f + expf(-a));
        }
        par ^= 1;
    }
}

// Stage F: out = sx + r * (vffn[l] @ kk). Rows are 32KB = 4 tiles of 8KB.
// grid = 148 x 256.
__global__ __launch_bounds__(256, 1) void kF(
    const float* __restrict__ vffn, float* __restrict__ xout, int l, int last)
{
    extern __shared__ __align__(16) float smem[];
    float4* bufs = (float4*)smem;
    float* s_kk = smem + 8 * 2 * 2048;   // 8192 f
    int tid = threadIdx.x, warp = tid >> 5, lane = tid & 31;

    for (int i = tid; i < H; i += 256) s_kk[i] = g_kk[i];
    __syncthreads();

    int gw = blockIdx.x * 8 + warp;
    float4* b0 = bufs + warp * 1024;
    float4* b1 = b0 + 512;
    // tiles t: output o = gw + (t>>2)*WTOT, seg = t&3
    int nouts = 0;
    for (int o = gw; o < D; o += WTOT) nouts++;
    int ntiles = 4 * nouts;
    if (ntiles > 0) {
        auto wsrc = [&](int t) -> const float4* {
            int o = gw + (t >> 2) * WTOT;
            int seg = t & 3;
            return (const float4*)(vffn + ((size_t)l * D + o) * H + seg * 2048);
        };
        cp_row8k(b0, wsrc(0), lane);
        float acc = 0.f;
        for (int t = 0; t < ntiles; t++) {
            if (t + 1 < ntiles) cp_row8k((t & 1) ? b0 : b1, wsrc(t + 1), lane);
            else cp_commit_empty();
            cp_wait1();
            const float4* vec = (const float4*)s_kk + (t & 3) * 512;
            acc += dot_row8k((t & 1) ? b1 : b0, vec, lane);
            if ((t & 3) == 3) {
                float a = warp_sum(acc);
                int o = gw + (t >> 2) * WTOT;
                if (lane == 0) {
                    float val = g_sx[o] + g_r[o] * a;
                    if (last) xout[o] = val;
                    else g_x[o] = val;
                }
                acc = 0.f;
            }
        }
    }
}

extern "C" void kernel_launch(void* const* d_in, const int* in_sizes, int n_in,
                              void* d_out, int out_size)
{
    const float* x      = (const float*)d_in[0];
    const float* state  = (const float*)d_in[1];
    const float* ln1w   = (const float*)d_in[2];
    const float* ln1b   = (const float*)d_in[3];
    const float* ln2w   = (const float*)d_in[4];
    const float* ln2b   = (const float*)d_in[5];
    const float* td     = (const float*)d_in[6];
    const float* tf     = (const float*)d_in[7];
    const float* key    = (const float*)d_in[8];
    const float* keymul = (const float*)d_in[9];
    const float* ow     = (const float*)d_in[10];
    const float* tmk    = (const float*)d_in[11];
    const float* tmr    = (const float*)d_in[12];
    const float* kffn   = (const float*)d_in[13];
    const float* rffn   = (const float*)d_in[14];
    const float* vffn   = (const float*)d_in[15];

    float* out       = (float*)d_out;
    float* out_x     = out;       // [D]
    float* out_state = out + D;   // [L*5*D]

    const int SM_B = (8 * 2 * 2048 + 2 * 2048) * 4;  // 147456
    const int SM_C = (8 * 2 * 2048 + 2048) * 4;      // 139264
    const int SM_E = (8 * 2 * 2048 + 2 * 2048) * 4;  // 147456
    const int SM_F = (8 * 2 * 2048 + 8192) * 4;      // 163840

    cudaFuncSetAttribute(kB, cudaFuncAttributeMaxDynamicSharedMemorySize, SM_B);
    cudaFuncSetAttribute(kC, cudaFuncAttributeMaxDynamicSharedMemorySize, SM_C);
    cudaFuncSetAttribute(kE, cudaFuncAttributeMaxDynamicSharedMemorySize, SM_E);
    cudaFuncSetAttribute(kF, cudaFuncAttributeMaxDynamicSharedMemorySize, SM_F);

    kcopy<<<(D + 255) / 256, 256>>>(x);
    for (int l = 0; l < NL; l++) {
        kB<<<GRID, 256, SM_B>>>(state, ln1w, ln1b, key, keymul, out_state, l);
        kC<<<GRID, 256, SM_C>>>(state, td, tf, ow, out_state, l);
        kE<<<GRID, 256, SM_E>>>(state, ln2w, ln2b, tmk, tmr, kffn, rffn, out_state, l);
        kF<<<GRID, 256, SM_F>>>(vffn, out_x, l, (l == NL - 1) ? 1 : 0);
    }
}

// round 9
// speedup vs baseline: 1.1735x; 1.0530x over previous
#include <cuda_runtime.h>
#include <cuda_bf16.h>
#include <math.h>
#include <stdint.h>

#define D 2048
#define H 8192
#define NL 4
#define GRID 148
#define NW 16
#define WTOT (GRID * NW)

// Scratch (device globals; no allocation allowed)
__device__ float g_x[D];          // current layer input
__device__ float g_rrk[3 * D];    // key@xn + keymul@state0 partials
__device__ float g_sx[D];         // x + rwkv
__device__ float g_kk[H];         // relu(kffn@dx)^2
__device__ float g_r[D];          // sigmoid(rffn@xr)

__device__ __forceinline__ float warp_sum(float v) {
#pragma unroll
    for (int o = 16; o; o >>= 1) v += __shfl_xor_sync(0xffffffffu, v, o);
    return v;
}

__device__ __forceinline__ float d4(const float4 a, const float4 b) {
    return a.x * b.x + a.y * b.y + a.z * b.z + a.w * b.w;
}

// 512-thread block sum
__device__ __forceinline__ float block_sum(float v, float* sred) {
    v = warp_sum(v);
    int w = threadIdx.x >> 5, lane = threadIdx.x & 31;
    if (lane == 0) sred[w] = v;
    __syncthreads();
    float t = (threadIdx.x < NW) ? sred[threadIdx.x] : 0.f;
    if (w == 0) {
        t = warp_sum(t);
        if (lane == 0) sred[0] = t;
    }
    __syncthreads();
    float r = sred[0];
    __syncthreads();
    return r;
}

// ---- cp.async warp-owned pipeline helpers (4KB tiles = 256 float4) ----
__device__ __forceinline__ void cp_tile4k(float4* sdst, const float4* __restrict__ gsrc,
                                          int lane) {
#pragma unroll
    for (int u = 0; u < 8; u++) {
        unsigned int s = (unsigned int)__cvta_generic_to_shared(sdst + lane + u * 32);
        asm volatile("cp.async.cg.shared.global [%0], [%1], 16;\n"
                     :: "r"(s), "l"(gsrc + lane + u * 32));
    }
    asm volatile("cp.async.commit_group;\n");
}
__device__ __forceinline__ void cp_commit_empty() {
    asm volatile("cp.async.commit_group;\n");
}
__device__ __forceinline__ void cp_wait1() {
    asm volatile("cp.async.wait_group 1;\n" ::: "memory");
    __syncwarp();
}

__device__ __forceinline__ float dot_tile4k(const float4* __restrict__ sbuf,
                                            const float4* __restrict__ svec, int lane) {
    float a0 = 0.f, a1 = 0.f, a2 = 0.f, a3 = 0.f;
#pragma unroll
    for (int u = 0; u < 8; u += 4) {
        a0 += d4(sbuf[lane + u * 32],       svec[lane + u * 32]);
        a1 += d4(sbuf[lane + (u + 1) * 32], svec[lane + (u + 1) * 32]);
        a2 += d4(sbuf[lane + (u + 2) * 32], svec[lane + (u + 2) * 32]);
        a3 += d4(sbuf[lane + (u + 3) * 32], svec[lane + (u + 3) * 32]);
    }
    return (a0 + a1) + (a2 + a3);
}

__global__ __launch_bounds__(256) void kcopy(const float* __restrict__ x) {
    int i = blockIdx.x * 256 + threadIdx.x;
    if (i < D) g_x[i] = x[i];
}

// Stage B: LN1 (redundant per block) + g_rrk = key@xn + keymul@state0.
// grid = 148 x 512. Warp tiles: pair p -> 4 tiles (key h0,h1; keymul h0,h1).
__global__ __launch_bounds__(512, 1) void kB(
    const float* __restrict__ state,
    const float* __restrict__ ln1w, const float* __restrict__ ln1b,
    const float* __restrict__ key, const float* __restrict__ keymul,
    float* __restrict__ out_state, int l)
{
    extern __shared__ __align__(16) float smem[];
    float4* bufs = (float4*)smem;            // NW warps * 512 f4 = 128KB
    float* s_xn = smem + NW * 2 * 1024;      // 2048 f
    float* s_sr = s_xn + 2048;               // 2048 f
    __shared__ float sred[NW + 1];
    int tid = threadIdx.x, warp = tid >> 5, lane = tid & 31;

    const float* srow = state + (size_t)(5 * l) * D;
    float ls = 0.f;
    for (int i = tid; i < D; i += 512) {
        float xv = g_x[i];
        s_xn[i] = xv; ls += xv;
        s_sr[i] = srow[i];
    }
    float m = block_sum(ls, sred) * (1.f / D);
    float lv = 0.f;
    for (int i = tid; i < D; i += 512) { float d0 = s_xn[i] - m; lv += d0 * d0; }
    float var = block_sum(lv, sred) * (1.f / D);
    float rs = rsqrtf(var + 1e-5f);
    const float* w = ln1w + (size_t)l * D;
    const float* b = ln1b + (size_t)l * D;
    for (int i = tid; i < D; i += 512)
        s_xn[i] = (s_xn[i] - m) * rs * w[i] + b[i];
    __syncthreads();
    if (blockIdx.x == 0) {
        float* xnrow = out_state + (size_t)(5 * l + 0) * D;
        for (int i = tid; i < D; i += 512) xnrow[i] = s_xn[i];
    }

    int gw = blockIdx.x * NW + warp;
    float4* b0 = bufs + warp * 512;
    float4* b1 = b0 + 256;
    const float4* xn4 = (const float4*)s_xn;
    const float4* sr4 = (const float4*)s_sr;
    int npairs = 0;
    for (int p = gw; p < 3 * D; p += WTOT) npairs++;
    int ntiles = 4 * npairs;
    if (ntiles > 0) {
        auto wsrc = [&](int t) -> const float4* {
            int p = gw + (t >> 2) * WTOT;
            int j = p >> 11, i = p & 2047;
            int sub = t & 3;
            const float* base = (sub < 2) ? key : keymul;
            return (const float4*)(base + ((((size_t)l * 3 + j) * D + i) * (size_t)D))
                   + (sub & 1) * 256;
        };
        cp_tile4k(b0, wsrc(0), lane);
        float acc = 0.f;
        for (int t = 0; t < ntiles; t++) {
            if (t + 1 < ntiles) cp_tile4k((t & 1) ? b0 : b1, wsrc(t + 1), lane);
            else cp_commit_empty();
            cp_wait1();
            int sub = t & 3;
            const float4* vec = ((sub < 2) ? xn4 : sr4) + (sub & 1) * 256;
            acc += dot_tile4k((t & 1) ? b1 : b0, vec, lane);
            if (sub == 3) {
                float a = warp_sum(acc);
                int p = gw + (t >> 2) * WTOT;
                if (lane == 0) g_rrk[p] = a;
                acc = 0.f;
            }
        }
    }
}

// Stage C: WKV epilogue (redundant per block) + sx = x + outputv[l] @ rab.
// grid = 148 x 512; warp owns at most one row (2 tiles).
__global__ __launch_bounds__(512, 1) void kC(
    const float* __restrict__ state,
    const float* __restrict__ td, const float* __restrict__ tf,
    const float* __restrict__ ow,
    float* __restrict__ out_state, int l)
{
    extern __shared__ __align__(16) float smem[];
    float4* bufs = (float4*)smem;
    float* s_v = smem + NW * 2 * 1024;  // rab vec
    int tid = threadIdx.x, warp = tid >> 5, lane = tid & 31;

    for (int i = tid; i < D; i += 512) {
        float k  = g_rrk[i];
        float v  = g_rrk[D + i];
        float rr = g_rrk[2 * D + i];
        float aa = state[(size_t)(5 * l + 1) * D + i];
        float bb = state[(size_t)(5 * l + 2) * D + i];
        float pp = state[(size_t)(5 * l + 3) * D + i];
        float tfi = tf[(size_t)l * D + i];
        float tdi = td[(size_t)l * D + i];
        float rsig = 1.f / (1.f + expf(-rr));
        float ww = tfi + k;
        float q = fmaxf(pp, ww);
        float e1 = expf(pp - q), e2 = expf(ww - q);
        float a_ = e1 * aa + e2 * v;
        float b_ = e1 * bb + e2;
        s_v[i] = rsig * (a_ / b_);
        if (blockIdx.x == 0) {
            float ww2 = pp + tdi;
            float q2 = fmaxf(ww2, k);
            float f1 = expf(ww2 - q2), f2 = expf(k - q2);
            out_state[(size_t)(5 * l + 1) * D + i] = f1 * aa + f2 * v;
            out_state[(size_t)(5 * l + 2) * D + i] = f1 * bb + f2;
            out_state[(size_t)(5 * l + 3) * D + i] = q2;
        }
    }
    __syncthreads();

    int gw = blockIdx.x * NW + warp;
    float4* b0 = bufs + warp * 512;
    float4* b1 = b0 + 256;
    const float4* vec = (const float4*)s_v;
    if (gw < D) {
        const float4* row = (const float4*)(ow + ((size_t)l * D + gw) * D);
        cp_tile4k(b0, row, lane);
        cp_tile4k(b1, row + 256, lane);
        asm volatile("cp.async.wait_group 1;\n" ::: "memory");
        __syncwarp();
        float a = dot_tile4k(b0, vec, lane);
        asm volatile("cp.async.wait_group 0;\n" ::: "memory");
        __syncwarp();
        a += dot_tile4k(b1, vec + 256, lane);
        a = warp_sum(a);
        if (lane == 0) g_sx[gw] = g_x[gw] + a;
    }
}

// Stage E: LN2 (redundant per block) + kk = relu(kffn@dx)^2 ; r = sigmoid(rffn@xr).
// grid = 148 x 512; row -> 2 tiles.
__global__ __launch_bounds__(512, 1) void kE(
    const float* __restrict__ state,
    const float* __restrict__ ln2w, const float* __restrict__ ln2b,
    const float* __restrict__ tmk, const float* __restrict__ tmr,
    const float* __restrict__ kffn, const float* __restrict__ rffn,
    float* __restrict__ out_state, int l)
{
    extern __shared__ __align__(16) float smem[];
    float4* bufs = (float4*)smem;
    float* s_dx = smem + NW * 2 * 1024;
    float* s_xr = s_dx + 2048;
    __shared__ float sred[NW + 1];
    int tid = threadIdx.x, warp = tid >> 5, lane = tid & 31;

    float ls = 0.f;
    for (int i = tid; i < D; i += 512) { float v = g_sx[i]; s_dx[i] = v; ls += v; }
    float m = block_sum(ls, sred) * (1.f / D);
    float lv = 0.f;
    for (int i = tid; i < D; i += 512) { float d0 = s_dx[i] - m; lv += d0 * d0; }
    float var = block_sum(lv, sred) * (1.f / D);
    float rs = rsqrtf(var + 1e-5f);
    const float* w  = ln2w + (size_t)l * D;
    const float* b  = ln2b + (size_t)l * D;
    const float* sf = state + (size_t)(5 * l + 4) * D;
    const float* tk = tmk + (size_t)l * D;
    const float* tr = tmr + (size_t)l * D;
    for (int i = tid; i < D; i += 512) {
        float x2n = (s_dx[i] - m) * rs * w[i] + b[i];
        float sfi = sf[i];
        if (blockIdx.x == 0) out_state[(size_t)(5 * l + 4) * D + i] = x2n;
        s_xr[i] = x2n + sfi * tr[i];
        s_dx[i] = x2n + sfi * tk[i];
    }
    __syncthreads();

    int gw = blockIdx.x * NW + warp;
    float4* b0 = bufs + warp * 512;
    float4* b1 = b0 + 256;
    const int NR = H + D;
    int nrows = 0;
    for (int r = gw; r < NR; r += WTOT) nrows++;
    int ntiles = 2 * nrows;
    if (ntiles > 0) {
        auto wsrc = [&](int t) -> const float4* {
            int r = gw + (t >> 1) * WTOT;
            const float4* base;
            if (r < H) base = (const float4*)(kffn + ((size_t)l * H + r) * D);
            else       base = (const float4*)(rffn + ((size_t)l * D + (r - H)) * D);
            return base + (t & 1) * 256;
        };
        cp_tile4k(b0, wsrc(0), lane);
        float acc = 0.f;
        for (int t = 0; t < ntiles; t++) {
            if (t + 1 < ntiles) cp_tile4k((t & 1) ? b0 : b1, wsrc(t + 1), lane);
            else cp_commit_empty();
            cp_wait1();
            int r = gw + (t >> 1) * WTOT;
            const float4* vec = (const float4*)(r < H ? s_dx : s_xr) + (t & 1) * 256;
            acc += dot_tile4k((t & 1) ? b1 : b0, vec, lane);
            if (t & 1) {
                float a = warp_sum(acc);
                if (lane == 0) {
                    if (r < H) { float rl = fmaxf(a, 0.f); g_kk[r] = rl * rl; }
                    else g_r[r - H] = 1.f / (1.f + expf(-a));
                }
                acc = 0.f;
            }
        }
    }
}

// Stage F: out = sx + r * (vffn[l] @ kk). Row = 32KB = 8 tiles.
// grid = 148 x 512.
__global__ __launch_bounds__(512, 1) void kF(
    const float* __restrict__ vffn, float* __restrict__ xout, int l, int last)
{
    extern __shared__ __align__(16) float smem[];
    float4* bufs = (float4*)smem;
    float* s_kk = smem + NW * 2 * 1024;   // 8192 f
    int tid = threadIdx.x, warp = tid >> 5, lane = tid & 31;

    for (int i = tid; i < H; i += 512) s_kk[i] = g_kk[i];
    __syncthreads();

    int gw = blockIdx.x * NW + warp;
    float4* b0 = bufs + warp * 512;
    float4* b1 = b0 + 256;
    if (gw < D) {
        const float4* row = (const float4*)(vffn + ((size_t)l * D + gw) * H);
        const float4* kv = (const float4*)s_kk;
        cp_tile4k(b0, row, lane);
        float acc = 0.f;
        for (int t = 0; t < 8; t++) {
            if (t + 1 < 8) cp_tile4k((t & 1) ? b0 : b1, row + (t + 1) * 256, lane);
            else cp_commit_empty();
            cp_wait1();
            acc += dot_tile4k((t & 1) ? b1 : b0, kv + t * 256, lane);
        }
        acc = warp_sum(acc);
        if (lane == 0) {
            float val = g_sx[gw] + g_r[gw] * acc;
            if (last) xout[gw] = val;
            else g_x[gw] = val;
        }
    }
}

extern "C" void kernel_launch(void* const* d_in, const int* in_sizes, int n_in,
                              void* d_out, int out_size)
{
    const float* x      = (const float*)d_in[0];
    const float* state  = (const float*)d_in[1];
    const float* ln1w   = (const float*)d_in[2];
    const float* ln1b   = (const float*)d_in[3];
    const float* ln2w   = (const float*)d_in[4];
    const float* ln2b   = (const float*)d_in[5];
    const float* td     = (const float*)d_in[6];
    const float* tf     = (const float*)d_in[7];
    const float* key    = (const float*)d_in[8];
    const float* keymul = (const float*)d_in[9];
    const float* ow     = (const float*)d_in[10];
    const float* tmk    = (const float*)d_in[11];
    const float* tmr    = (const float*)d_in[12];
    const float* kffn   = (const float*)d_in[13];
    const float* rffn   = (const float*)d_in[14];
    const float* vffn   = (const float*)d_in[15];

    float* out       = (float*)d_out;
    float* out_x     = out;       // [D]
    float* out_state = out + D;   // [L*5*D]

    const int BUF = NW * 2 * 1024 * 4;               // 131072 B = 128KB buffers
    const int SM_B = BUF + 2 * 2048 * 4;             // 147456
    const int SM_C = BUF + 2048 * 4;                 // 139264
    const int SM_E = BUF + 2 * 2048 * 4;             // 147456
    const int SM_F = BUF + 8192 * 4;                 // 163840

    cudaFuncSetAttribute(kB, cudaFuncAttributeMaxDynamicSharedMemorySize, SM_B);
    cudaFuncSetAttribute(kC, cudaFuncAttributeMaxDynamicSharedMemorySize, SM_C);
    cudaFuncSetAttribute(kE, cudaFuncAttributeMaxDynamicSharedMemorySize, SM_E);
    cudaFuncSetAttribute(kF, cudaFuncAttributeMaxDynamicSharedMemorySize, SM_F);

    kcopy<<<(D + 255) / 256, 256>>>(x);
    for (int l = 0; l < NL; l++) {
        kB<<<GRID, 512, SM_B>>>(state, ln1w, ln1b, key, keymul, out_state, l);
        kC<<<GRID, 512, SM_C>>>(state, td, tf, ow, out_state, l);
        kE<<<GRID, 512, SM_E>>>(state, ln2w, ln2b, tmk, tmr, kffn, rffn, out_state, l);
        kF<<<GRID, 512, SM_F>>>(vffn, out_x, l, (l == NL - 1) ? 1 : 0);
    }
}

// round 10
// speedup vs baseline: 1.2556x; 1.0699x over previous
#include <cuda_runtime.h>
#include <cuda_bf16.h>
#include <math.h>
#include <stdint.h>

#define D 2048
#define H 8192
#define NL 4
#define GRID 148

// Scratch (device globals; no allocation allowed)
__device__ float g_x[D];          // current layer input
__device__ float g_rrk[3 * D];    // key@xn + keymul@state0
__device__ float g_sx[D];         // x + rwkv
__device__ float g_kk[H];         // relu(kffn@dx)^2
__device__ float g_r[D];          // sigmoid(rffn@xr)

__device__ __forceinline__ float warp_sum(float v) {
#pragma unroll
    for (int o = 16; o; o >>= 1) v += __shfl_xor_sync(0xffffffffu, v, o);
    return v;
}

__device__ __forceinline__ float d4(const float4 a, const float4 b) {
    return a.x * b.x + a.y * b.y + a.z * b.z + a.w * b.w;
}

// 512-thread block sum
__device__ __forceinline__ float block_sum(float v, float* sred) {
    v = warp_sum(v);
    int w = threadIdx.x >> 5, lane = threadIdx.x & 31;
    if (lane == 0) sred[w] = v;
    __syncthreads();
    float t = (threadIdx.x < 16) ? sred[threadIdx.x] : 0.f;
    if (w == 0) {
        t = warp_sum(t);
        if (lane == 0) sred[0] = t;
    }
    __syncthreads();
    float r = sred[0];
    __syncthreads();
    return r;
}

// ---- mbarrier + bulk-DMA helpers ----
__device__ __forceinline__ unsigned smem_u32(const void* p) {
    return (unsigned)__cvta_generic_to_shared(p);
}
__device__ __forceinline__ void mbar_init(unsigned mbar, unsigned count) {
    asm volatile("mbarrier.init.shared.b64 [%0], %1;" :: "r"(mbar), "r"(count) : "memory");
}
__device__ __forceinline__ void mbar_expect_tx(unsigned mbar, unsigned bytes) {
    asm volatile("mbarrier.arrive.expect_tx.shared.b64 _, [%0], %1;"
                 :: "r"(mbar), "r"(bytes) : "memory");
}
__device__ __forceinline__ void bulk_g2s(unsigned sdst, const void* gsrc,
                                         unsigned bytes, unsigned mbar) {
    asm volatile("cp.async.bulk.shared::cluster.global.mbarrier::complete_tx::bytes "
                 "[%0], [%1], %2, [%3];"
                 :: "r"(sdst), "l"(gsrc), "r"(bytes), "r"(mbar) : "memory");
}
__device__ __forceinline__ void mbar_wait(unsigned mbar, unsigned parity) {
    asm volatile(
        "{\n\t"
        ".reg .pred P1;\n\t"
        "WAIT_%=:\n\t"
        "mbarrier.try_wait.parity.acquire.cta.shared::cta.b64 P1, [%0], %1, 0x989680;\n\t"
        "@P1 bra DONE_%=;\n\t"
        "bra WAIT_%=;\n\t"
        "DONE_%=:\n\t"
        "}"
        :: "r"(mbar), "r"(parity) : "memory");
}

__global__ __launch_bounds__(256) void kcopy(const float* __restrict__ x) {
    int i = blockIdx.x * 256 + threadIdx.x;
    if (i < D) g_x[i] = x[i];
}

// ============ Stage B: LN1 + g_rrk = key@xn + keymul@state0 ============
// chunk = 4 key rows (32KB) + 4 keymul rows (32KB); NC = 3*D/4 = 1536.
__global__ __launch_bounds__(512, 1) void kB(
    const float* __restrict__ state,
    const float* __restrict__ ln1w, const float* __restrict__ ln1b,
    const float* __restrict__ key, const float* __restrict__ keymul,
    float* __restrict__ out_state, int l)
{
    extern __shared__ __align__(16) float smem[];
    float4* bufs4 = (float4*)smem;           // 2 x 4096 f4 (2 x 64KB)
    float* s_xn = smem + 32768;              // 2048 f
    float* s_sr = s_xn + 2048;               // 2048 f
    __shared__ float sred[17];
    __shared__ float s_part[2][16];
    __shared__ unsigned long long s_mbar[2];
    int tid = threadIdx.x, warp = tid >> 5, lane = tid & 31;
    const int NC = 3 * D / 4;
    int bk = blockIdx.x;
    const float* kbase = key    + (size_t)l * 3 * D * D;
    const float* mbase = keymul + (size_t)l * 3 * D * D;
    unsigned mb[2] = { smem_u32(&s_mbar[0]), smem_u32(&s_mbar[1]) };
    unsigned ba[2] = { smem_u32(bufs4), smem_u32(bufs4 + 4096) };

    if (tid == 0) { mbar_init(mb[0], 1); mbar_init(mb[1], 1); }
    __syncthreads();
    if (tid == 0) {
#pragma unroll
        for (int q = 0; q < 2; q++) {
            int c = bk + q * GRID;
            if (c < NC) {
                mbar_expect_tx(mb[q], 65536);
                bulk_g2s(ba[q],         kbase + (size_t)c * 4 * D, 32768, mb[q]);
                bulk_g2s(ba[q] + 32768, mbase + (size_t)c * 4 * D, 32768, mb[q]);
            }
        }
    }

    // LN1 prologue (overlaps with first DMA)
    const float* srow = state + (size_t)(5 * l) * D;
    float ls = 0.f;
    for (int i = tid; i < D; i += 512) {
        float xv = g_x[i];
        s_xn[i] = xv; ls += xv;
        s_sr[i] = srow[i];
    }
    float m = block_sum(ls, sred) * (1.f / D);
    float lv = 0.f;
    for (int i = tid; i < D; i += 512) { float d0 = s_xn[i] - m; lv += d0 * d0; }
    float var = block_sum(lv, sred) * (1.f / D);
    float rs = rsqrtf(var + 1e-5f);
    const float* w = ln1w + (size_t)l * D;
    const float* b = ln1b + (size_t)l * D;
    for (int i = tid; i < D; i += 512)
        s_xn[i] = (s_xn[i] - m) * rs * w[i] + b[i];
    __syncthreads();
    if (bk == 0) {
        float* xnrow = out_state + (size_t)(5 * l + 0) * D;
        for (int i = tid; i < D; i += 512) xnrow[i] = s_xn[i];
    }

    const float4* xn4 = (const float4*)s_xn;
    const float4* sr4 = (const float4*)s_sr;
    unsigned ph[2] = { 0, 0 };
    int ci = 0;
    for (int c = bk; c < NC; c += GRID, ci++) {
        int bsl = ci & 1;
        mbar_wait(mb[bsl], ph[bsl]); ph[bsl] ^= 1;
        // warp w<8: key row (w>>1), half (w&1); w>=8: keymul
        int iskm = warp >> 3, w2 = warp & 7;
        const float4* B = bufs4 + bsl * 4096 + iskm * 2048 + (w2 >> 1) * 512 + (w2 & 1) * 256;
        const float4* V = (iskm ? sr4 : xn4) + (w2 & 1) * 256;
        float a0 = 0.f, a1 = 0.f;
#pragma unroll
        for (int u = 0; u < 8; u += 2) {
            a0 += d4(B[lane + u * 32],       V[lane + u * 32]);
            a1 += d4(B[lane + (u + 1) * 32], V[lane + (u + 1) * 32]);
        }
        float s = warp_sum(a0 + a1);
        if (lane == 0) s_part[bsl][warp] = s;
        __syncthreads();
        if (tid < 4) {
            int p = c * 4 + tid;
            g_rrk[p] = s_part[bsl][2 * tid] + s_part[bsl][2 * tid + 1]
                     + s_part[bsl][8 + 2 * tid] + s_part[bsl][8 + 2 * tid + 1];
        }
        int cn = c + 2 * GRID;
        if (tid == 0 && cn < NC) {
            mbar_expect_tx(mb[bsl], 65536);
            bulk_g2s(ba[bsl],         kbase + (size_t)cn * 4 * D, 32768, mb[bsl]);
            bulk_g2s(ba[bsl] + 32768, mbase + (size_t)cn * 4 * D, 32768, mb[bsl]);
        }
    }
}

// ============ Stage C: WKV epilogue + sx = x + outputv[l] @ rab ============
// chunk = 4 rows (32KB); NC = 512. Buffers 2 x 32KB.
__global__ __launch_bounds__(512, 1) void kC(
    const float* __restrict__ state,
    const float* __restrict__ td, const float* __restrict__ tf,
    const float* __restrict__ ow,
    float* __restrict__ out_state, int l)
{
    extern __shared__ __align__(16) float smem[];
    float4* bufs4 = (float4*)smem;           // 2 x 2048 f4
    float* s_v = smem + 16384;               // 2048 f
    __shared__ float s_part[2][16];
    __shared__ unsigned long long s_mbar[2];
    int tid = threadIdx.x, warp = tid >> 5, lane = tid & 31;
    const int NC = D / 4;
    int bk = blockIdx.x;
    const float* obase = ow + (size_t)l * D * D;
    unsigned mb[2] = { smem_u32(&s_mbar[0]), smem_u32(&s_mbar[1]) };
    unsigned ba[2] = { smem_u32(bufs4), smem_u32(bufs4 + 2048) };

    if (tid == 0) { mbar_init(mb[0], 1); mbar_init(mb[1], 1); }
    __syncthreads();
    if (tid == 0) {
#pragma unroll
        for (int q = 0; q < 2; q++) {
            int c = bk + q * GRID;
            if (c < NC) {
                mbar_expect_tx(mb[q], 32768);
                bulk_g2s(ba[q], obase + (size_t)c * 4 * D, 32768, mb[q]);
            }
        }
    }

    // WKV epilogue -> s_v (rab), block 0 writes state rows 1-3
    for (int i = tid; i < D; i += 512) {
        float k  = g_rrk[i];
        float v  = g_rrk[D + i];
        float rr = g_rrk[2 * D + i];
        float aa = state[(size_t)(5 * l + 1) * D + i];
        float bb = state[(size_t)(5 * l + 2) * D + i];
        float pp = state[(size_t)(5 * l + 3) * D + i];
        float tfi = tf[(size_t)l * D + i];
        float tdi = td[(size_t)l * D + i];
        float rsig = 1.f / (1.f + expf(-rr));
        float ww = tfi + k;
        float q = fmaxf(pp, ww);
        float e1 = expf(pp - q), e2 = expf(ww - q);
        float a_ = e1 * aa + e2 * v;
        float b_ = e1 * bb + e2;
        s_v[i] = rsig * (a_ / b_);
        if (bk == 0) {
            float ww2 = pp + tdi;
            float q2 = fmaxf(ww2, k);
            float f1 = expf(ww2 - q2), f2 = expf(k - q2);
            out_state[(size_t)(5 * l + 1) * D + i] = f1 * aa + f2 * v;
            out_state[(size_t)(5 * l + 2) * D + i] = f1 * bb + f2;
            out_state[(size_t)(5 * l + 3) * D + i] = q2;
        }
    }
    __syncthreads();

    const float4* v4 = (const float4*)s_v;
    unsigned ph[2] = { 0, 0 };
    int ci = 0;
    for (int c = bk; c < NC; c += GRID, ci++) {
        int bsl = ci & 1;
        mbar_wait(mb[bsl], ph[bsl]); ph[bsl] ^= 1;
        // warp: row (warp>>2), quarter (warp&3) of 512 floats = 128 f4
        const float4* B = bufs4 + bsl * 2048 + (warp >> 2) * 512 + (warp & 3) * 128;
        const float4* V = v4 + (warp & 3) * 128;
        float a0 = 0.f, a1 = 0.f;
#pragma unroll
        for (int u = 0; u < 4; u += 2) {
            a0 += d4(B[lane + u * 32],       V[lane + u * 32]);
            a1 += d4(B[lane + (u + 1) * 32], V[lane + (u + 1) * 32]);
        }
        float s = warp_sum(a0 + a1);
        if (lane == 0) s_part[bsl][warp] = s;
        __syncthreads();
        if (tid < 4) {
            int o = c * 4 + tid;
            float a = s_part[bsl][4 * tid] + s_part[bsl][4 * tid + 1]
                    + s_part[bsl][4 * tid + 2] + s_part[bsl][4 * tid + 3];
            g_sx[o] = g_x[o] + a;
        }
        int cn = c + 2 * GRID;
        if (tid == 0 && cn < NC) {
            mbar_expect_tx(mb[bsl], 32768);
            bulk_g2s(ba[bsl], obase + (size_t)cn * 4 * D, 32768, mb[bsl]);
        }
    }
}

// ============ Stage E: LN2 + kk = relu(kffn@dx)^2 ; r = sigmoid(rffn@xr) ============
// chunk = 8 rows (64KB); NC = (H+D)/8 = 1280 (chunks 0..1023 kffn, 1024.. rffn).
__global__ __launch_bounds__(512, 1) void kE(
    const float* __restrict__ state,
    const float* __restrict__ ln2w, const float* __restrict__ ln2b,
    const float* __restrict__ tmk, const float* __restrict__ tmr,
    const float* __restrict__ kffn, const float* __restrict__ rffn,
    float* __restrict__ out_state, int l)
{
    extern __shared__ __align__(16) float smem[];
    float4* bufs4 = (float4*)smem;           // 2 x 4096 f4
    float* s_dx = smem + 32768;
    float* s_xr = s_dx + 2048;
    __shared__ float sred[17];
    __shared__ float s_part[2][16];
    __shared__ unsigned long long s_mbar[2];
    int tid = threadIdx.x, warp = tid >> 5, lane = tid & 31;
    const int NC = (H + D) / 8;
    const int NCK = H / 8;   // 1024
    int bk = blockIdx.x;
    const float* kbase = kffn + (size_t)l * H * D;
    const float* rbase = rffn + (size_t)l * D * D;
    unsigned mb[2] = { smem_u32(&s_mbar[0]), smem_u32(&s_mbar[1]) };
    unsigned ba[2] = { smem_u32(bufs4), smem_u32(bufs4 + 4096) };

    if (tid == 0) { mbar_init(mb[0], 1); mbar_init(mb[1], 1); }
    __syncthreads();
    if (tid == 0) {
#pragma unroll
        for (int q = 0; q < 2; q++) {
            int c = bk + q * GRID;
            if (c < NC) {
                const float* src = (c < NCK) ? kbase + (size_t)c * 8 * D
                                             : rbase + (size_t)(c - NCK) * 8 * D;
                mbar_expect_tx(mb[q], 65536);
                bulk_g2s(ba[q], src, 65536, mb[q]);
            }
        }
    }

    // LN2 prologue
    float ls = 0.f;
    for (int i = tid; i < D; i += 512) { float v = g_sx[i]; s_dx[i] = v; ls += v; }
    float m = block_sum(ls, sred) * (1.f / D);
    float lv = 0.f;
    for (int i = tid; i < D; i += 512) { float d0 = s_dx[i] - m; lv += d0 * d0; }
    float var = block_sum(lv, sred) * (1.f / D);
    float rs = rsqrtf(var + 1e-5f);
    const float* w  = ln2w + (size_t)l * D;
    const float* b  = ln2b + (size_t)l * D;
    const float* sf = state + (size_t)(5 * l + 4) * D;
    const float* tk = tmk + (size_t)l * D;
    const float* tr = tmr + (size_t)l * D;
    for (int i = tid; i < D; i += 512) {
        float x2n = (s_dx[i] - m) * rs * w[i] + b[i];
        float sfi = sf[i];
        if (bk == 0) out_state[(size_t)(5 * l + 4) * D + i] = x2n;
        s_xr[i] = x2n + sfi * tr[i];
        s_dx[i] = x2n + sfi * tk[i];
    }
    __syncthreads();

    const float4* dx4 = (const float4*)s_dx;
    const float4* xr4 = (const float4*)s_xr;
    unsigned ph[2] = { 0, 0 };
    int ci = 0;
    for (int c = bk; c < NC; c += GRID, ci++) {
        int bsl = ci & 1;
        mbar_wait(mb[bsl], ph[bsl]); ph[bsl] ^= 1;
        // warp: row (warp>>1), half (warp&1)
        const float4* B = bufs4 + bsl * 4096 + (warp >> 1) * 512 + (warp & 1) * 256;
        const float4* V = ((c < NCK) ? dx4 : xr4) + (warp & 1) * 256;
        float a0 = 0.f, a1 = 0.f;
#pragma unroll
        for (int u = 0; u < 8; u += 2) {
            a0 += d4(B[lane + u * 32],       V[lane + u * 32]);
            a1 += d4(B[lane + (u + 1) * 32], V[lane + (u + 1) * 32]);
        }
        float s = warp_sum(a0 + a1);
        if (lane == 0) s_part[bsl][warp] = s;
        __syncthreads();
        if (tid < 8) {
            float v = s_part[bsl][2 * tid] + s_part[bsl][2 * tid + 1];
            int r = c * 8 + tid;
            if (r < H) { float rl = fmaxf(v, 0.f); g_kk[r] = rl * rl; }
            else g_r[r - H] = 1.f / (1.f + expf(-v));
        }
        int cn = c + 2 * GRID;
        if (tid == 0 && cn < NC) {
            const float* src = (cn < NCK) ? kbase + (size_t)cn * 8 * D
                                          : rbase + (size_t)(cn - NCK) * 8 * D;
            mbar_expect_tx(mb[bsl], 65536);
            bulk_g2s(ba[bsl], src, 65536, mb[bsl]);
        }
    }
}

// ============ Stage F: out = sx + r * (vffn[l] @ kk) ============
// chunk = 2 rows (64KB); NC = D/2 = 1024.
__global__ __launch_bounds__(512, 1) void kF(
    const float* __restrict__ vffn, float* __restrict__ xout, int l, int last)
{
    extern __shared__ __align__(16) float smem[];
    float4* bufs4 = (float4*)smem;           // 2 x 4096 f4
    float* s_kk = smem + 32768;              // 8192 f
    __shared__ float s_part[2][16];
    __shared__ unsigned long long s_mbar[2];
    int tid = threadIdx.x, warp = tid >> 5, lane = tid & 31;
    const int NC = D / 2;
    int bk = blockIdx.x;
    const float* vbase = vffn + (size_t)l * D * H;
    unsigned mb[2] = { smem_u32(&s_mbar[0]), smem_u32(&s_mbar[1]) };
    unsigned ba[2] = { smem_u32(bufs4), smem_u32(bufs4 + 4096) };

    if (tid == 0) { mbar_init(mb[0], 1); mbar_init(mb[1], 1); }
    __syncthreads();
    if (tid == 0) {
#pragma unroll
        for (int q = 0; q < 2; q++) {
            int c = bk + q * GRID;
            if (c < NC) {
                mbar_expect_tx(mb[q], 65536);
                bulk_g2s(ba[q], vbase + (size_t)c * 2 * H, 65536, mb[q]);
            }
        }
    }

    for (int i = tid; i < H; i += 512) s_kk[i] = g_kk[i];
    __syncthreads();

    const float4* kk4 = (const float4*)s_kk;
    unsigned ph[2] = { 0, 0 };
    int ci = 0;
    for (int c = bk; c < NC; c += GRID, ci++) {
        int bsl = ci & 1;
        mbar_wait(mb[bsl], ph[bsl]); ph[bsl] ^= 1;
        // warp: row (warp>>3), eighth (warp&7) of 8192 floats
        const float4* B = bufs4 + bsl * 4096 + (warp >> 3) * 2048 + (warp & 7) * 256;
        const float4* V = kk4 + (warp & 7) * 256;
        float a0 = 0.f, a1 = 0.f;
#pragma unroll
        for (int u = 0; u < 8; u += 2) {
            a0 += d4(B[lane + u * 32],       V[lane + u * 32]);
            a1 += d4(B[lane + (u + 1) * 32], V[lane + (u + 1) * 32]);
        }
        float s = warp_sum(a0 + a1);
        if (lane == 0) s_part[bsl][warp] = s;
        __syncthreads();
        if (tid < 2) {
            float a = 0.f;
#pragma unroll
            for (int e = 0; e < 8; e++) a += s_part[bsl][8 * tid + e];
            int o = c * 2 + tid;
            float val = g_sx[o] + g_r[o] * a;
            if (last) xout[o] = val;
            else g_x[o] = val;
        }
        int cn = c + 2 * GRID;
        if (tid == 0 && cn < NC) {
            mbar_expect_tx(mb[bsl], 65536);
            bulk_g2s(ba[bsl], vbase + (size_t)cn * 2 * H, 65536, mb[bsl]);
        }
    }
}

extern "C" void kernel_launch(void* const* d_in, const int* in_sizes, int n_in,
                              void* d_out, int out_size)
{
    const float* x      = (const float*)d_in[0];
    const float* state  = (const float*)d_in[1];
    const float* ln1w   = (const float*)d_in[2];
    const float* ln1b   = (const float*)d_in[3];
    const float* ln2w   = (const float*)d_in[4];
    const float* ln2b   = (const float*)d_in[5];
    const float* td     = (const float*)d_in[6];
    const float* tf     = (const float*)d_in[7];
    const float* key    = (const float*)d_in[8];
    const float* keymul = (const float*)d_in[9];
    const float* ow     = (const float*)d_in[10];
    const float* tmk    = (const float*)d_in[11];
    const float* tmr    = (const float*)d_in[12];
    const float* kffn   = (const float*)d_in[13];
    const float* rffn   = (const float*)d_in[14];
    const float* vffn   = (const float*)d_in[15];

    float* out       = (float*)d_out;
    float* out_x     = out;       // [D]
    float* out_state = out + D;   // [L*5*D]

    const int SM_B = (32768 + 4096) * 4;   // 147456
    const int SM_C = (16384 + 2048) * 4;   // 73728
    const int SM_E = (32768 + 4096) * 4;   // 147456
    const int SM_F = (32768 + 8192) * 4;   // 163840

    cudaFuncSetAttribute(kB, cudaFuncAttributeMaxDynamicSharedMemorySize, SM_B);
    cudaFuncSetAttribute(kC, cudaFuncAttributeMaxDynamicSharedMemorySize, SM_C);
    cudaFuncSetAttribute(kE, cudaFuncAttributeMaxDynamicSharedMemorySize, SM_E);
    cudaFuncSetAttribute(kF, cudaFuncAttributeMaxDynamicSharedMemorySize, SM_F);

    kcopy<<<(D + 255) / 256, 256>>>(x);
    for (int l = 0; l < NL; l++) {
        kB<<<GRID, 512, SM_B>>>(state, ln1w, ln1b, key, keymul, out_state, l);
        kC<<<GRID, 512, SM_C>>>(state, td, tf, ow, out_state, l);
        kE<<<GRID, 512, SM_E>>>(state, ln2w, ln2b, tmk, tmr, kffn, rffn, out_state, l);
        kF<<<GRID, 512, SM_F>>>(vffn, out_x, l, (l == NL - 1) ? 1 : 0);
    }
}

// round 11
// speedup vs baseline: 1.3063x; 1.0404x over previous
#include <cuda_runtime.h>
#include <cuda_bf16.h>
#include <math.h>
#include <stdint.h>

#define D 2048
#define H 8192
#define NL 4
#define GRID 148
#define NW 16
#define WTOT (GRID * NW)

// Scratch (device globals; no allocation allowed)
__device__ float g_x[D];          // current layer input
__device__ float g_rrk[3 * D];    // key@xn + keymul@state0
__device__ float g_sx[D];         // x + rwkv
__device__ float g_kk[H];         // relu(kffn@dx)^2
__device__ float g_r[D];          // sigmoid(rffn@xr)

__device__ __forceinline__ float warp_sum(float v) {
#pragma unroll
    for (int o = 16; o; o >>= 1) v += __shfl_xor_sync(0xffffffffu, v, o);
    return v;
}

__device__ __forceinline__ float d4(const float4 a, const float4 b) {
    return a.x * b.x + a.y * b.y + a.z * b.z + a.w * b.w;
}

// 512-thread block sum
__device__ __forceinline__ float block_sum(float v, float* sred) {
    v = warp_sum(v);
    int w = threadIdx.x >> 5, lane = threadIdx.x & 31;
    if (lane == 0) sred[w] = v;
    __syncthreads();
    float t = (threadIdx.x < NW) ? sred[threadIdx.x] : 0.f;
    if (w == 0) {
        t = warp_sum(t);
        if (lane == 0) sred[0] = t;
    }
    __syncthreads();
    float r = sred[0];
    __syncthreads();
    return r;
}

// ---- mbarrier + bulk-DMA helpers ----
__device__ __forceinline__ unsigned smem_u32(const void* p) {
    return (unsigned)__cvta_generic_to_shared(p);
}
__device__ __forceinline__ void mbar_init(unsigned mbar, unsigned count) {
    asm volatile("mbarrier.init.shared.b64 [%0], %1;" :: "r"(mbar), "r"(count) : "memory");
}
__device__ __forceinline__ void mbar_expect_tx(unsigned mbar, unsigned bytes) {
    asm volatile("mbarrier.arrive.expect_tx.shared.b64 _, [%0], %1;"
                 :: "r"(mbar), "r"(bytes) : "memory");
}
__device__ __forceinline__ void bulk_g2s(unsigned sdst, const void* gsrc,
                                         unsigned bytes, unsigned mbar) {
    asm volatile("cp.async.bulk.shared::cluster.global.mbarrier::complete_tx::bytes "
                 "[%0], [%1], %2, [%3];"
                 :: "r"(sdst), "l"(gsrc), "r"(bytes), "r"(mbar) : "memory");
}
__device__ __forceinline__ void mbar_wait(unsigned mbar, unsigned parity) {
    asm volatile(
        "{\n\t"
        ".reg .pred P1;\n\t"
        "WAIT_%=:\n\t"
        "mbarrier.try_wait.parity.acquire.cta.shared::cta.b64 P1, [%0], %1, 0x989680;\n\t"
        "@P1 bra DONE_%=;\n\t"
        "bra WAIT_%=;\n\t"
        "DONE_%=:\n\t"
        "}"
        :: "r"(mbar), "r"(parity) : "memory");
}

// 4KB tile dot: 256 f4, 8 per lane, 4 accumulators.
__device__ __forceinline__ float dot_tile4k(const float4* __restrict__ sbuf,
                                            const float4* __restrict__ svec, int lane) {
    float a0 = 0.f, a1 = 0.f, a2 = 0.f, a3 = 0.f;
#pragma unroll
    for (int u = 0; u < 8; u += 4) {
        a0 += d4(sbuf[lane + u * 32],       svec[lane + u * 32]);
        a1 += d4(sbuf[lane + (u + 1) * 32], svec[lane + (u + 1) * 32]);
        a2 += d4(sbuf[lane + (u + 2) * 32], svec[lane + (u + 2) * 32]);
        a3 += d4(sbuf[lane + (u + 3) * 32], svec[lane + (u + 3) * 32]);
    }
    return (a0 + a1) + (a2 + a3);
}

__global__ __launch_bounds__(256) void kcopy(const float* __restrict__ x) {
    int i = blockIdx.x * 256 + threadIdx.x;
    if (i < D) g_x[i] = x[i];
}

// ============ Stage B: LN1 + g_rrk = key@xn + keymul@state0 ============
// Warp owns pairs p = gw + k*WTOT; pair = key row (2 tiles, vec xn) + keymul row (2 tiles, vec sr).
__global__ __launch_bounds__(512, 1) void kB(
    const float* __restrict__ state,
    const float* __restrict__ ln1w, const float* __restrict__ ln1b,
    const float* __restrict__ key, const float* __restrict__ keymul,
    float* __restrict__ out_state, int l)
{
    extern __shared__ __align__(16) float smem[];
    float4* bufs = (float4*)smem;            // 16 warps * 512 f4 = 128KB
    float* s_xn = smem + 32768;              // 2048 f
    float* s_sr = s_xn + 2048;               // 2048 f
    __shared__ float sred[NW + 1];
    __shared__ __align__(8) unsigned long long s_mbar[2 * NW];
    int tid = threadIdx.x, warp = tid >> 5, lane = tid & 31;
    int gw = blockIdx.x * NW + warp;
    const float* kbase = key    + (size_t)l * 3 * D * D;
    const float* mbase = keymul + (size_t)l * 3 * D * D;
    float4* wbuf = bufs + warp * 512;
    unsigned mb[2] = { smem_u32(&s_mbar[2 * warp]), smem_u32(&s_mbar[2 * warp + 1]) };

    if (tid < 2 * NW) mbar_init(smem_u32(&s_mbar[tid]), 1);
    __syncthreads();

    int npairs = 0;
    for (int p = gw; p < 3 * D; p += WTOT) npairs++;
    int ntiles = 4 * npairs;
    auto src = [&](int t) -> const float4* {
        int p = gw + (t >> 2) * WTOT;
        int sub = t & 3;
        const float* base = (sub < 2) ? kbase : mbase;
        return (const float4*)(base + (size_t)p * D) + (sub & 1) * 256;
    };
    if (lane == 0) {
#pragma unroll
        for (int q = 0; q < 2; q++) if (q < ntiles) {
            mbar_expect_tx(mb[q], 4096);
            bulk_g2s(smem_u32(wbuf + q * 256), src(q), 4096, mb[q]);
        }
    }

    // LN1 prologue (overlaps the first DMAs)
    const float* srow = state + (size_t)(5 * l) * D;
    float ls = 0.f;
    for (int i = tid; i < D; i += 512) {
        float xv = g_x[i];
        s_xn[i] = xv; ls += xv;
        s_sr[i] = srow[i];
    }
    float m = block_sum(ls, sred) * (1.f / D);
    float lv = 0.f;
    for (int i = tid; i < D; i += 512) { float d0 = s_xn[i] - m; lv += d0 * d0; }
    float var = block_sum(lv, sred) * (1.f / D);
    float rs = rsqrtf(var + 1e-5f);
    const float* w = ln1w + (size_t)l * D;
    const float* b = ln1b + (size_t)l * D;
    for (int i = tid; i < D; i += 512)
        s_xn[i] = (s_xn[i] - m) * rs * w[i] + b[i];
    __syncthreads();
    if (blockIdx.x == 0) {
        float* xnrow = out_state + (size_t)(5 * l + 0) * D;
        for (int i = tid; i < D; i += 512) xnrow[i] = s_xn[i];
    }

    const float4* xn4 = (const float4*)s_xn;
    const float4* sr4 = (const float4*)s_sr;
    unsigned ph0 = 0, ph1 = 0;
    float acc = 0.f;
    for (int t = 0; t < ntiles; t++) {
        int sl = t & 1;
        if (sl == 0) { mbar_wait(mb[0], ph0); ph0 ^= 1; }
        else         { mbar_wait(mb[1], ph1); ph1 ^= 1; }
        int sub = t & 3;
        const float4* V = ((sub < 2) ? xn4 : sr4) + (sub & 1) * 256;
        acc += dot_tile4k(wbuf + sl * 256, V, lane);
        __syncwarp();
        int tn = t + 2;
        if (lane == 0 && tn < ntiles) {
            mbar_expect_tx(mb[sl], 4096);
            bulk_g2s(smem_u32(wbuf + sl * 256), src(tn), 4096, mb[sl]);
        }
        if (sub == 3) {
            float a = warp_sum(acc);
            if (lane == 0) g_rrk[gw + (t >> 2) * WTOT] = a;
            acc = 0.f;
        }
    }
}

// ============ Stage C: WKV epilogue + sx = x + outputv[l] @ rab ============
// Warp owns rows r = gw + k*WTOT (8KB = 2 tiles).
__global__ __launch_bounds__(512, 1) void kC(
    const float* __restrict__ state,
    const float* __restrict__ td, const float* __restrict__ tf,
    const float* __restrict__ ow,
    float* __restrict__ out_state, int l)
{
    extern __shared__ __align__(16) float smem[];
    float4* bufs = (float4*)smem;
    float* s_v = smem + 32768;   // 2048 f
    __shared__ __align__(8) unsigned long long s_mbar[2 * NW];
    int tid = threadIdx.x, warp = tid >> 5, lane = tid & 31;
    int gw = blockIdx.x * NW + warp;
    const float* obase = ow + (size_t)l * D * D;
    float4* wbuf = bufs + warp * 512;
    unsigned mb[2] = { smem_u32(&s_mbar[2 * warp]), smem_u32(&s_mbar[2 * warp + 1]) };

    if (tid < 2 * NW) mbar_init(smem_u32(&s_mbar[tid]), 1);
    __syncthreads();

    int nrows = 0;
    for (int r = gw; r < D; r += WTOT) nrows++;
    int ntiles = 2 * nrows;
    auto src = [&](int t) -> const float4* {
        int r = gw + (t >> 1) * WTOT;
        return (const float4*)(obase + (size_t)r * D) + (t & 1) * 256;
    };
    if (lane == 0) {
#pragma unroll
        for (int q = 0; q < 2; q++) if (q < ntiles) {
            mbar_expect_tx(mb[q], 4096);
            bulk_g2s(smem_u32(wbuf + q * 256), src(q), 4096, mb[q]);
        }
    }

    // WKV epilogue -> s_v (rab); block 0 writes state rows 1-3
    for (int i = tid; i < D; i += 512) {
        float k  = g_rrk[i];
        float v  = g_rrk[D + i];
        float rr = g_rrk[2 * D + i];
        float aa = state[(size_t)(5 * l + 1) * D + i];
        float bb = state[(size_t)(5 * l + 2) * D + i];
        float pp = state[(size_t)(5 * l + 3) * D + i];
        float tfi = tf[(size_t)l * D + i];
        float tdi = td[(size_t)l * D + i];
        float rsig = 1.f / (1.f + expf(-rr));
        float ww = tfi + k;
        float q = fmaxf(pp, ww);
        float e1 = expf(pp - q), e2 = expf(ww - q);
        float a_ = e1 * aa + e2 * v;
        float b_ = e1 * bb + e2;
        s_v[i] = rsig * (a_ / b_);
        if (blockIdx.x == 0) {
            float ww2 = pp + tdi;
            float q2 = fmaxf(ww2, k);
            float f1 = expf(ww2 - q2), f2 = expf(k - q2);
            out_state[(size_t)(5 * l + 1) * D + i] = f1 * aa + f2 * v;
            out_state[(size_t)(5 * l + 2) * D + i] = f1 * bb + f2;
            out_state[(size_t)(5 * l + 3) * D + i] = q2;
        }
    }
    __syncthreads();

    const float4* v4 = (const float4*)s_v;
    unsigned ph0 = 0, ph1 = 0;
    float acc = 0.f;
    for (int t = 0; t < ntiles; t++) {
        int sl = t & 1;
        if (sl == 0) { mbar_wait(mb[0], ph0); ph0 ^= 1; }
        else         { mbar_wait(mb[1], ph1); ph1 ^= 1; }
        acc += dot_tile4k(wbuf + sl * 256, v4 + (t & 1) * 256, lane);
        __syncwarp();
        int tn = t + 2;
        if (lane == 0 && tn < ntiles) {
            mbar_expect_tx(mb[sl], 4096);
            bulk_g2s(smem_u32(wbuf + sl * 256), src(tn), 4096, mb[sl]);
        }
        if (t & 1) {
            float a = warp_sum(acc);
            int r = gw + (t >> 1) * WTOT;
            if (lane == 0) g_sx[r] = g_x[r] + a;
            acc = 0.f;
        }
    }
}

// ============ Stage E: LN2 + kk = relu(kffn@dx)^2 ; r = sigmoid(rffn@xr) ============
// Warp owns rows r = gw + k*WTOT over H+D rows (8KB = 2 tiles each).
__global__ __launch_bounds__(512, 1) void kE(
    const float* __restrict__ state,
    const float* __restrict__ ln2w, const float* __restrict__ ln2b,
    const float* __restrict__ tmk, const float* __restrict__ tmr,
    const float* __restrict__ kffn, const float* __restrict__ rffn,
    float* __restrict__ out_state, int l)
{
    extern __shared__ __align__(16) float smem[];
    float4* bufs = (float4*)smem;
    float* s_dx = smem + 32768;
    float* s_xr = s_dx + 2048;
    __shared__ float sred[NW + 1];
    __shared__ __align__(8) unsigned long long s_mbar[2 * NW];
    int tid = threadIdx.x, warp = tid >> 5, lane = tid & 31;
    int gw = blockIdx.x * NW + warp;
    const float* kbase = kffn + (size_t)l * H * D;
    const float* rbase = rffn + (size_t)l * D * D;
    float4* wbuf = bufs + warp * 512;
    unsigned mb[2] = { smem_u32(&s_mbar[2 * warp]), smem_u32(&s_mbar[2 * warp + 1]) };

    if (tid < 2 * NW) mbar_init(smem_u32(&s_mbar[tid]), 1);
    __syncthreads();

    const int NR = H + D;
    int nrows = 0;
    for (int r = gw; r < NR; r += WTOT) nrows++;
    int ntiles = 2 * nrows;
    auto src = [&](int t) -> const float4* {
        int r = gw + (t >> 1) * WTOT;
        const float* base = (r < H) ? kbase + (size_t)r * D : rbase + (size_t)(r - H) * D;
        return (const float4*)base + (t & 1) * 256;
    };
    if (lane == 0) {
#pragma unroll
        for (int q = 0; q < 2; q++) if (q < ntiles) {
            mbar_expect_tx(mb[q], 4096);
            bulk_g2s(smem_u32(wbuf + q * 256), src(q), 4096, mb[q]);
        }
    }

    // LN2 prologue (overlaps first DMAs)
    float ls = 0.f;
    for (int i = tid; i < D; i += 512) { float v = g_sx[i]; s_dx[i] = v; ls += v; }
    float m = block_sum(ls, sred) * (1.f / D);
    float lv = 0.f;
    for (int i = tid; i < D; i += 512) { float d0 = s_dx[i] - m; lv += d0 * d0; }
    float var = block_sum(lv, sred) * (1.f / D);
    float rs = rsqrtf(var + 1e-5f);
    const float* w  = ln2w + (size_t)l * D;
    const float* b  = ln2b + (size_t)l * D;
    const float* sf = state + (size_t)(5 * l + 4) * D;
    const float* tk = tmk + (size_t)l * D;
    const float* tr = tmr + (size_t)l * D;
    for (int i = tid; i < D; i += 512) {
        float x2n = (s_dx[i] - m) * rs * w[i] + b[i];
        float sfi = sf[i];
        if (blockIdx.x == 0) out_state[(size_t)(5 * l + 4) * D + i] = x2n;
        s_xr[i] = x2n + sfi * tr[i];
        s_dx[i] = x2n + sfi * tk[i];
    }
    __syncthreads();

    const float4* dx4 = (const float4*)s_dx;
    const float4* xr4 = (const float4*)s_xr;
    unsigned ph0 = 0, ph1 = 0;
    float acc = 0.f;
    for (int t = 0; t < ntiles; t++) {
        int sl = t & 1;
        if (sl == 0) { mbar_wait(mb[0], ph0); ph0 ^= 1; }
        else         { mbar_wait(mb[1], ph1); ph1 ^= 1; }
        int r = gw + (t >> 1) * WTOT;
        const float4* V = ((r < H) ? dx4 : xr4) + (t & 1) * 256;
        acc += dot_tile4k(wbuf + sl * 256, V, lane);
        __syncwarp();
        int tn = t + 2;
        if (lane == 0 && tn < ntiles) {
            mbar_expect_tx(mb[sl], 4096);
            bulk_g2s(smem_u32(wbuf + sl * 256), src(tn), 4096, mb[sl]);
        }
        if (t & 1) {
            float a = warp_sum(acc);
            if (lane == 0) {
                if (r < H) { float rl = fmaxf(a, 0.f); g_kk[r] = rl * rl; }
                else g_r[r - H] = 1.f / (1.f + expf(-a));
            }
            acc = 0.f;
        }
    }
}

// ============ Stage F: out = sx + r * (vffn[l] @ kk) ============
// Warp owns rows r = gw + k*WTOT (32KB = 8 tiles each).
__global__ __launch_bounds__(512, 1) void kF(
    const float* __restrict__ vffn, float* __restrict__ xout, int l, int last)
{
    extern __shared__ __align__(16) float smem[];
    float4* bufs = (float4*)smem;
    float* s_kk = smem + 32768;   // 8192 f
    __shared__ __align__(8) unsigned long long s_mbar[2 * NW];
    int tid = threadIdx.x, warp = tid >> 5, lane = tid & 31;
    int gw = blockIdx.x * NW + warp;
    const float* vbase = vffn + (size_t)l * D * H;
    float4* wbuf = bufs + warp * 512;
    unsigned mb[2] = { smem_u32(&s_mbar[2 * warp]), smem_u32(&s_mbar[2 * warp + 1]) };

    if (tid < 2 * NW) mbar_init(smem_u32(&s_mbar[tid]), 1);
    __syncthreads();

    int nrows = 0;
    for (int r = gw; r < D; r += WTOT) nrows++;
    int ntiles = 8 * nrows;
    auto src = [&](int t) -> const float4* {
        int r = gw + (t >> 3) * WTOT;
        return (const float4*)(vbase + (size_t)r * H) + (t & 7) * 256;
    };
    if (lane == 0) {
#pragma unroll
        for (int q = 0; q < 2; q++) if (q < ntiles) {
            mbar_expect_tx(mb[q], 4096);
            bulk_g2s(smem_u32(wbuf + q * 256), src(q), 4096, mb[q]);
        }
    }

    for (int i = tid; i < H; i += 512) s_kk[i] = g_kk[i];
    __syncthreads();

    const float4* kk4 = (const float4*)s_kk;
    unsigned ph0 = 0, ph1 = 0;
    float acc = 0.f;
    for (int t = 0; t < ntiles; t++) {
        int sl = t & 1;
        if (sl == 0) { mbar_wait(mb[0], ph0); ph0 ^= 1; }
        else         { mbar_wait(mb[1], ph1); ph1 ^= 1; }
        acc += dot_tile4k(wbuf + sl * 256, kk4 + (t & 7) * 256, lane);
        __syncwarp();
        int tn = t + 2;
        if (lane == 0 && tn < ntiles) {
            mbar_expect_tx(mb[sl], 4096);
            bulk_g2s(smem_u32(wbuf + sl * 256), src(tn), 4096, mb[sl]);
        }
        if ((t & 7) == 7) {
            float a = warp_sum(acc);
            int r = gw + (t >> 3) * WTOT;
            if (lane == 0) {
                float val = g_sx[r] + g_r[r] * a;
                if (last) xout[r] = val;
                else g_x[r] = val;
            }
            acc = 0.f;
        }
    }
}

extern "C" void kernel_launch(void* const* d_in, const int* in_sizes, int n_in,
                              void* d_out, int out_size)
{
    const float* x      = (const float*)d_in[0];
    const float* state  = (const float*)d_in[1];
    const float* ln1w   = (const float*)d_in[2];
    const float* ln1b   = (const float*)d_in[3];
    const float* ln2w   = (const float*)d_in[4];
    const float* ln2b   = (const float*)d_in[5];
    const float* td     = (const float*)d_in[6];
    const float* tf     = (const float*)d_in[7];
    const float* key    = (const float*)d_in[8];
    const float* keymul = (const float*)d_in[9];
    const float* ow     = (const float*)d_in[10];
    const float* tmk    = (const float*)d_in[11];
    const float* tmr    = (const float*)d_in[12];
    const float* kffn   = (const float*)d_in[13];
    const float* rffn   = (const float*)d_in[14];
    const float* vffn   = (const float*)d_in[15];

    float* out       = (float*)d_out;
    float* out_x     = out;       // [D]
    float* out_state = out + D;   // [L*5*D]

    const int SM_B = (32768 + 4096) * 4;   // 147456
    const int SM_C = (32768 + 2048) * 4;   // 139264
    const int SM_E = (32768 + 4096) * 4;   // 147456
    const int SM_F = (32768 + 8192) * 4;   // 163840

    cudaFuncSetAttribute(kB, cudaFuncAttributeMaxDynamicSharedMemorySize, SM_B);
    cudaFuncSetAttribute(kC, cudaFuncAttributeMaxDynamicSharedMemorySize, SM_C);
    cudaFuncSetAttribute(kE, cudaFuncAttributeMaxDynamicSharedMemorySize, SM_E);
    cudaFuncSetAttribute(kF, cudaFuncAttributeMaxDynamicSharedMemorySize, SM_F);

    kcopy<<<(D + 255) / 256, 256>>>(x);
    for (int l = 0; l < NL; l++) {
        kB<<<GRID, 512, SM_B>>>(state, ln1w, ln1b, key, keymul, out_state, l);
        kC<<<GRID, 512, SM_C>>>(state, td, tf, ow, out_state, l);
        kE<<<GRID, 512, SM_E>>>(state, ln2w, ln2b, tmk, tmr, kffn, rffn, out_state, l);
        kF<<<GRID, 512, SM_F>>>(vffn, out_x, l, (l == NL - 1) ? 1 : 0);
    }
}